// round 13
// baseline (speedup 1.0000x reference)
#include <cuda_runtime.h>
#include <cuda_bf16.h>

// FastSpeech2 hard duration-based frame->token scalar averaging.
//   d_in[0] frame_scalar      float32 [B, 8192]
//   d_in[1] duration          float32 [B, 1024]
//   d_in[2] frame_scalar_len  int32   [B]
//   d_in[3] duration_len      int32   [B]
// Output: token_scalar float32 [B, 1024] (+ optional duration_len as f32 [B]).
//
// R13: R12 (bounded reads + scan-free direct segment-sum gather) with
//  1) PAD(+1/32) skewed smem buffer -> the stride-~8 gather becomes
//     conflict-free (unpadded R12 gather was 8-way conflicted), staged via
//     batched LDG.128 -> 4x STS (cp.async can't hit the skewed layout).
//  2) SPEC_BLOCKS=4: ~75% of rows have their whole frame region in flight
//     before the duration cumsum resolves (no serialized tail round-trip).

#define TFR 8192
#define TTK 1024
#define NTHREADS 256
#define CHT 4                    // tokens per thread
#define NWARPS (NTHREADS / 32)
#define SPEC 4                   // speculative 1024-float blocks
#define MAXBLK 8

// +1 float per 32: stride-8 lane patterns map onto all 32 banks.
__device__ __forceinline__ int PAD(int i) { return i + (i >> 5); }
#define BUF_SLOTS (TFR - 1 + ((TFR - 1) >> 5) + 1)   // PAD(8191)+1 = 8447

__global__ __launch_bounds__(NTHREADS, 6)
void fs2_dur_avg_kernel(const float* __restrict__ frame_scalar,
                        const float* __restrict__ duration,
                        const int*   __restrict__ frame_scalar_len,
                        const int*   __restrict__ duration_len,
                        float*       __restrict__ out,
                        int B, int write_extra)
{
    __shared__ float s_buf[BUF_SLOTS];   // skewed frame row
    __shared__ float s_dwsum[NWARPS];    // duration warp totals

    const int row  = blockIdx.x;
    const int tid  = threadIdx.x;
    const int lane = tid & 31;
    const int wid  = tid >> 5;

    const float4* fs4 = reinterpret_cast<const float4*>(
        frame_scalar + (size_t)row * TFR);

    // ---- speculative batched LDG.128 of first SPEC blocks -----------------
    // (independent loads issue back-to-back; data lands while the duration
    //  cumsum below runs)
    float4 sv[SPEC];
    #pragma unroll
    for (int k = 0; k < SPEC; k++)
        sv[k] = fs4[tid + (k << 8)];                 // coalesced 512B/warp

    // ---- duration load + per-thread/warp cumsum ---------------------------
    const float4 d4 = reinterpret_cast<const float4*>(
                          duration + (size_t)row * TTK)[tid];
    const int   dl = duration_len[row];
    const float fl = (float)frame_scalar_len[row];

    float dv[CHT], p[CHT], d_excl;
    {
        const float din[CHT] = {d4.x, d4.y, d4.z, d4.w};
        const int jbase = tid * CHT;
        #pragma unroll
        for (int k = 0; k < CHT; k++) {
            // round half-to-even (jnp.round), clamp >=0, zero past dlen
            const float r = fmaxf(rintf(din[k]), 0.0f);
            dv[k] = (jbase + k < dl) ? r : 0.0f;
        }
        float run = 0.0f;
        #pragma unroll
        for (int k = 0; k < CHT; k++) { run += dv[k]; p[k] = run; }
        float incl = run;
        #pragma unroll
        for (int d = 1; d < 32; d <<= 1) {
            const float t = __shfl_up_sync(0xffffffffu, incl, d);
            if (lane >= d) incl += t;
        }
        if (lane == 31) s_dwsum[wid] = incl;
        d_excl = incl - run;                 // exclusive offset within warp
    }

    // ---- store speculative blocks into the skewed buffer ------------------
    #pragma unroll
    for (int k = 0; k < SPEC; k++) {
        const int fidx = ((k << 8) + tid) * 4;
        s_buf[PAD(fidx + 0)] = sv[k].x;
        s_buf[PAD(fidx + 1)] = sv[k].y;
        s_buf[PAD(fidx + 2)] = sv[k].z;
        s_buf[PAD(fidx + 3)] = sv[k].w;
    }
    __syncthreads();                         // s_dwsum + spec staging visible

    // Total duration + this thread's cross-warp offset (ascending order,
    // exact integer-valued sums -> deterministic).
    float dur_total = 0.0f;
    float doff = d_excl;
    #pragma unroll
    for (int i = 0; i < NWARPS; i++) {
        const float v = s_dwsum[i];
        dur_total += v;
        if (i < wid) doff += v;
    }

    // Frames actually referenced: indices < needed.
    const int needed = (int)fminf(dur_total, fl);
    const int kmax   = (needed + 1023) >> 10;        // 1024-float blocks

    // ---- tail blocks (25% of rows): batched predicated LDG.128 -> STS -----
    if (kmax > SPEC) {                               // uniform branch
        float4 tv[MAXBLK - SPEC];
        #pragma unroll
        for (int k = 0; k < MAXBLK - SPEC; k++)
            if (SPEC + k < kmax)
                tv[k] = fs4[tid + ((SPEC + k) << 8)];
        #pragma unroll
        for (int k = 0; k < MAXBLK - SPEC; k++)
            if (SPEC + k < kmax) {
                const int fidx = (((SPEC + k) << 8) + tid) * 4;
                s_buf[PAD(fidx + 0)] = tv[k].x;
                s_buf[PAD(fidx + 1)] = tv[k].y;
                s_buf[PAD(fidx + 2)] = tv[k].z;
                s_buf[PAD(fidx + 3)] = tv[k].w;
            }
    }
    __syncthreads();                         // full staging visible

    // ---- gather: direct segment sums from the skewed buffer ---------------
    {
        float4 res;
        float* rp = reinterpret_cast<float*>(&res);
        #pragma unroll
        for (int k = 0; k < CHT; k++) {
            const float cend_raw   = doff + p[k];       // cumsum thru token j
            const float cstart_raw = cend_raw - dv[k];  // cumsum thru j-1
            const float endf   = fminf(cend_raw, fl);
            const float startf = fminf(cstart_raw, fl);
            const float dlen_f = endf - startf;         // exact int-valued
            const int e = (int)endf;                    // e <= needed
            const int s = (int)startf;
            float sum = 0.0f;
            for (int i = s; i < e; i++) sum += s_buf[PAD(i)];
            rp[k] = (dlen_f > 0.0f) ? sum / fmaxf(dlen_f, 1.0f) : 0.0f;
        }
        reinterpret_cast<float4*>(out + (size_t)row * TTK)[tid] = res;
    }

    // Optional second tuple output: duration_len (numeric cast to f32).
    if (write_extra && tid == 0)
        out[(size_t)B * TTK + row] = (float)dl;
}

extern "C" void kernel_launch(void* const* d_in, const int* in_sizes, int n_in,
                              void* d_out, int out_size) {
    const float* frame_scalar     = (const float*)d_in[0];
    const float* duration         = (const float*)d_in[1];
    const int*   frame_scalar_len = (const int*)d_in[2];
    const int*   duration_len     = (const int*)d_in[3];
    float* out = (float*)d_out;

    const int B = in_sizes[2];                       // [B] int32
    const int write_extra = (out_size > B * TTK) ? 1 : 0;

    fs2_dur_avg_kernel<<<B, NTHREADS>>>(frame_scalar, duration,
                                        frame_scalar_len, duration_len,
                                        out, B, write_extra);
}

// round 15
// speedup vs baseline: 1.1400x; 1.1400x over previous
#include <cuda_runtime.h>
#include <cuda_bf16.h>

// FastSpeech2 hard duration-based frame->token scalar averaging.
//   d_in[0] frame_scalar      float32 [B, 8192]
//   d_in[1] duration          float32 [B, 1024]
//   d_in[2] frame_scalar_len  int32   [B]
//   d_in[3] duration_len      int32   [B]
// Output: token_scalar float32 [B, 1024] (+ optional duration_len as f32 [B]).
//
// R14 = champion R12 with ONE change: SPEC_BLOCKS 2 -> 4 (still cp.async).
// P(needed<=4096) ~ 0.75, so 75% of rows have their whole frame region in
// flight before the duration cumsum resolves -> no serialized tail DRAM
// round-trip. Everything else identical to the 14.7us kernel.

#define TFR 8192
#define TTK 1024
#define NTHREADS 256
#define CHT 4                    // tokens per thread
#define NWARPS (NTHREADS / 32)
#define SPEC_BLOCKS 4            // speculative 1024-float blocks

__global__ __launch_bounds__(NTHREADS)
void fs2_dur_avg_kernel(const float* __restrict__ frame_scalar,
                        const float* __restrict__ duration,
                        const int*   __restrict__ frame_scalar_len,
                        const int*   __restrict__ duration_len,
                        float*       __restrict__ out,
                        int B, int write_extra)
{
    __shared__ __align__(16) float s_buf[TFR];   // staged frame row (plain)
    __shared__ float s_dwsum[NWARPS];            // duration warp totals

    const int row  = blockIdx.x;
    const int tid  = threadIdx.x;
    const int lane = tid & 31;
    const int wid  = tid >> 5;

    const float* fsrow = frame_scalar + (size_t)row * TFR;
    const unsigned smb = (unsigned)__cvta_generic_to_shared(s_buf);

    // ---- speculative cp.async of first SPEC_BLOCKS frame blocks ----------
    // (fire-and-forget; overlaps the duration load + cumsum below)
    #pragma unroll
    for (int k = 0; k < SPEC_BLOCKS; k++) {
        const int idx = (k << 10) + (tid << 2);          // k*1024 + tid*4
        asm volatile("cp.async.cg.shared.global [%0], [%1], 16;\n"
                     :: "r"(smb + idx * 4), "l"(fsrow + idx));
    }
    asm volatile("cp.async.commit_group;\n");

    // ---- duration load + per-thread/warp cumsum ---------------------------
    const float4 d4 = reinterpret_cast<const float4*>(
                          duration + (size_t)row * TTK)[tid];
    const int   dl = duration_len[row];
    const float fl = (float)frame_scalar_len[row];

    float dv[CHT], p[CHT], d_excl;
    {
        const float din[CHT] = {d4.x, d4.y, d4.z, d4.w};
        const int jbase = tid * CHT;
        #pragma unroll
        for (int k = 0; k < CHT; k++) {
            // round half-to-even (jnp.round), clamp >=0, zero past dlen
            const float r = fmaxf(rintf(din[k]), 0.0f);
            dv[k] = (jbase + k < dl) ? r : 0.0f;
        }
        float run = 0.0f;
        #pragma unroll
        for (int k = 0; k < CHT; k++) { run += dv[k]; p[k] = run; }
        float incl = run;
        #pragma unroll
        for (int d = 1; d < 32; d <<= 1) {
            const float t = __shfl_up_sync(0xffffffffu, incl, d);
            if (lane >= d) incl += t;
        }
        if (lane == 31) s_dwsum[wid] = incl;
        d_excl = incl - run;                 // exclusive offset within warp
    }
    __syncthreads();                         // s_dwsum visible

    // Total duration + this thread's cross-warp offset (ascending order,
    // exact integer-valued sums -> deterministic).
    float dur_total = 0.0f;
    float doff = d_excl;
    #pragma unroll
    for (int i = 0; i < NWARPS; i++) {
        const float v = s_dwsum[i];
        dur_total += v;
        if (i < wid) doff += v;
    }

    // Frames actually referenced: indices < needed.
    const int needed = (int)fminf(dur_total, fl);
    const int kmax   = (needed + 1023) >> 10;        // 1024-float blocks

    // ---- stage remaining needed blocks (cp.async, all in flight) ----------
    for (int k = SPEC_BLOCKS; k < kmax; k++) {
        const int idx = (k << 10) + (tid << 2);
        asm volatile("cp.async.cg.shared.global [%0], [%1], 16;\n"
                     :: "r"(smb + idx * 4), "l"(fsrow + idx));
    }
    asm volatile("cp.async.commit_group;\n");
    asm volatile("cp.async.wait_group 0;\n");        // all staging complete
    __syncthreads();

    // ---- gather: direct segment sums from smem ----------------------------
    {
        float4 res;
        float* rp = reinterpret_cast<float*>(&res);
        #pragma unroll
        for (int k = 0; k < CHT; k++) {
            const float cend_raw   = doff + p[k];       // cumsum thru token j
            const float cstart_raw = cend_raw - dv[k];  // cumsum thru j-1
            const float endf   = fminf(cend_raw, fl);
            const float startf = fminf(cstart_raw, fl);
            const float dlen_f = endf - startf;         // exact int-valued
            const int e = (int)endf;                    // e <= needed
            const int s = (int)startf;
            float sum = 0.0f;
            for (int i = s; i < e; i++) sum += s_buf[i];
            rp[k] = (dlen_f > 0.0f) ? sum / fmaxf(dlen_f, 1.0f) : 0.0f;
        }
        reinterpret_cast<float4*>(out + (size_t)row * TTK)[tid] = res;
    }

    // Optional second tuple output: duration_len (numeric cast to f32).
    if (write_extra && tid == 0)
        out[(size_t)B * TTK + row] = (float)dl;
}

extern "C" void kernel_launch(void* const* d_in, const int* in_sizes, int n_in,
                              void* d_out, int out_size) {
    const float* frame_scalar     = (const float*)d_in[0];
    const float* duration         = (const float*)d_in[1];
    const int*   frame_scalar_len = (const int*)d_in[2];
    const int*   duration_len     = (const int*)d_in[3];
    float* out = (float*)d_out;

    const int B = in_sizes[2];                       // [B] int32
    const int write_extra = (out_size > B * TTK) ? 1 : 0;

    fs2_dur_avg_kernel<<<B, NTHREADS>>>(frame_scalar, duration,
                                        frame_scalar_len, duration_len,
                                        out, B, write_extra);
}